// round 3
// baseline (speedup 1.0000x reference)
#include <cuda_runtime.h>
#include <math.h>

// Problem constants (fixed shapes)
#define T_STEPS 2048
#define BATCH   256
#define HID     256
#define OUT_DIM 16

// Scratch (device globals: allocation-free kernel_launch)
__device__ float g_xp[134217728];      // [T][B][H] = 2048*256*256 floats = 512 MB
__device__ float g_hfinal[BATCH * HID];

// ---------------------------------------------------------------------------
// f32x2 packed-FMA helpers (sm_103a packed fp32 pipe; 2 fp32 FMA per issue)
// ---------------------------------------------------------------------------
__device__ __forceinline__ unsigned long long f32x2_dup(float w) {
    unsigned long long r;
    unsigned int u = __float_as_uint(w);
    asm("mov.b64 %0, {%1, %1};" : "=l"(r) : "r"(u));
    return r;
}
__device__ __forceinline__ unsigned long long f32x2_pack(float x, float y) {
    unsigned long long r;
    asm("mov.b64 %0, {%1, %2};" : "=l"(r) : "r"(__float_as_uint(x)), "r"(__float_as_uint(y)));
    return r;
}
__device__ __forceinline__ void f32x2_unpack(unsigned long long v, float& x, float& y) {
    unsigned int lo, hi;
    asm("mov.b64 {%0, %1}, %2;" : "=r"(lo), "=r"(hi) : "l"(v));
    x = __uint_as_float(lo);
    y = __uint_as_float(hi);
}
__device__ __forceinline__ void ffma2(unsigned long long& acc,
                                      unsigned long long a, unsigned long long b) {
    asm("fma.rn.f32x2 %0, %1, %2, %0;" : "+l"(acc) : "l"(a), "l"(b));
}

// ---------------------------------------------------------------------------
// Kernel 1: xp[t][b][h] = sum_i x[b][t][i] * W_ih[i][h] + b_h[h]
// 128x128x8 SGEMM, 256 threads, 8x8 microtile, f32x2-packed over j-pairs.
// ---------------------------------------------------------------------------
#define BM 128
#define BN 128
#define BK 8

__global__ __launch_bounds__(256)
void gemm_xp_kernel(const float* __restrict__ x,
                    const float* __restrict__ Wih,
                    const float* __restrict__ bh) {
    __shared__ __align__(16) float As[BK][BM];   // A tile, k-major (transposed on store)
    __shared__ __align__(16) float Bs[BK][BN];

    const int tid = threadIdx.x;
    const int tx = tid & 15;       // 0..15 (n direction)
    const int ty = tid >> 4;       // 0..15 (m direction)

    const size_t r0 = (size_t)blockIdx.x * BM;
    const int    n0 = blockIdx.y * BN;

    // A load mapping: 128 rows x 8 k = 1024 floats -> 1 float4/thread
    const int arow = tid >> 1;
    const int akq  = (tid & 1) * 4;
    // B load mapping: 8 k-rows x 128 n
    const int bkr = tid >> 5;
    const int bn  = (tid & 31) * 4;

    // acc2[i][q] = packed (C[i][2q], C[i][2q+1])
    unsigned long long acc2[8][4];
#pragma unroll
    for (int i = 0; i < 8; i++)
#pragma unroll
        for (int q = 0; q < 4; q++) acc2[i][q] = 0ull;

    for (int kt = 0; kt < 256; kt += BK) {
        float4 av = *(const float4*)&x[(r0 + arow) * 256 + kt + akq];
        float4 bv = *(const float4*)&Wih[(size_t)(kt + bkr) * 256 + n0 + bn];
        __syncthreads();   // previous tile's compute done before overwrite
        As[akq + 0][arow] = av.x;
        As[akq + 1][arow] = av.y;
        As[akq + 2][arow] = av.z;
        As[akq + 3][arow] = av.w;
        *(float4*)&Bs[bkr][bn] = bv;
        __syncthreads();
#pragma unroll
        for (int kk = 0; kk < BK; kk++) {
            float a[8];
            *(float4*)(a)     = *(const float4*)&As[kk][ty * 8];
            *(float4*)(a + 4) = *(const float4*)&As[kk][ty * 8 + 4];
            ulonglong2 b01 = *(const ulonglong2*)&Bs[kk][tx * 8];       // (b0,b1),(b2,b3)
            ulonglong2 b23 = *(const ulonglong2*)&Bs[kk][tx * 8 + 4];   // (b4,b5),(b6,b7)
#pragma unroll
            for (int i = 0; i < 8; i++) {
                unsigned long long ad = f32x2_dup(a[i]);
                ffma2(acc2[i][0], ad, b01.x);
                ffma2(acc2[i][1], ad, b01.y);
                ffma2(acc2[i][2], ad, b23.x);
                ffma2(acc2[i][3], ad, b23.y);
            }
        }
    }

    float bias[8];
    *(float4*)(bias)     = *(const float4*)&bh[n0 + tx * 8];
    *(float4*)(bias + 4) = *(const float4*)&bh[n0 + tx * 8 + 4];

#pragma unroll
    for (int i = 0; i < 8; i++) {
        size_t r = r0 + ty * 8 + i;
        int t = (int)(r & 2047);   // r % T
        int b = (int)(r >> 11);    // r / T
        size_t cbase = ((size_t)t * BATCH + b) * HID + n0 + tx * 8;
        float c[8];
#pragma unroll
        for (int q = 0; q < 4; q++)
            f32x2_unpack(acc2[i][q], c[2 * q], c[2 * q + 1]);
        float4 o0, o1;
        o0.x = c[0] + bias[0];  o0.y = c[1] + bias[1];
        o0.z = c[2] + bias[2];  o0.w = c[3] + bias[3];
        o1.x = c[4] + bias[4];  o1.y = c[5] + bias[5];
        o1.z = c[6] + bias[6];  o1.w = c[7] + bias[7];
        *(float4*)&g_xp[cbase]     = o0;
        *(float4*)&g_xp[cbase + 4] = o1;
    }
}

// ---------------------------------------------------------------------------
// Kernel 2: persistent recurrence. 128 CTAs, 2 batches each, 256 threads.
// Thread j owns output column j for both batches.
// k-pair packed f32x2: acc = (sum over even-k lanes, odd-k lanes);
// W pairs come directly from k-quad smem as u64 (no dup MOVs);
// h stored per-batch contiguous -> broadcast LDS.128 yields 2 k-pairs.
// W_hh rows [0,216) in smem, rows [216,256) as packed u64 pairs in registers.
// Dynamic smem: 216*256*4 + 4*256*4 = 221184 + 4096 = 225280 bytes.
// ---------------------------------------------------------------------------
#define KSM 216
#define KG  54          // KSM/4 (k-quad groups in smem)
#define KRG 40          // 256 - KSM (k rows in registers)
#define KRP 20          // KRG/2 (register u64 pairs)

__global__ __launch_bounds__(256, 1)
void rnn_recurrence_kernel(const float* __restrict__ W_hh) {
    extern __shared__ __align__(16) float smem[];
    float* Wq  = smem;                       // [KG][256] float4-quads: Wq[g*1024 + j*4 + kk]
    float* h0A = smem + KSM * 256;           // [256] batch0 buffer A
    float* h1A = h0A + 256;                  // [256] batch1 buffer A
    float* h0B = h1A + 256;
    float* h1B = h0B + 256;

    const int j  = threadIdx.x;
    const int b0 = blockIdx.x * 2;

    // Load W_hh rows [0,216) into k-quad layout: Wq[g][j][kk] = W[4g+kk][j]
    for (int idx = j; idx < KSM * 256; idx += 256) {
        int k  = idx >> 8;
        int jj = idx & 255;
        Wq[(k >> 2) * 1024 + jj * 4 + (k & 3)] = W_hh[idx];
    }
    // Rows [216,256): column j as packed k-pairs in registers
    unsigned long long wreg[KRP];
#pragma unroll
    for (int r = 0; r < KRP; r++)
        wreg[r] = f32x2_pack(W_hh[(KSM + 2 * r) * 256 + j],
                             W_hh[(KSM + 2 * r + 1) * 256 + j]);

    h0A[j] = 0.f;
    h1A[j] = 0.f;
    __syncthreads();

    float* h0c = h0A; float* h1c = h1A;
    float* h0n = h0B; float* h1n = h1B;

    const float* xp = g_xp + (size_t)b0 * HID + j;
    float p0 = xp[0];
    float p1 = xp[HID];

    for (int t = 0; t < T_STEPS; t++) {
        unsigned long long accA = f32x2_pack(p0, 0.f);
        unsigned long long accB = f32x2_pack(p1, 0.f);

        // software-prefetch next step's xp (hidden behind the k-loop)
        int tn = (t + 1 < T_STEPS) ? (t + 1) : t;
        p0 = xp[(size_t)tn * (BATCH * HID)];
        p1 = xp[(size_t)tn * (BATCH * HID) + HID];

        const unsigned long long* wp = (const unsigned long long*)(Wq + j * 4);
#pragma unroll 6
        for (int g = 0; g < KG; g++) {
            // w.x = (W[4g][j], W[4g+1][j]); w.y = (W[4g+2][j], W[4g+3][j])
            ulonglong2 w  = *(const ulonglong2*)&wp[g * 512];
            // broadcast: 4 consecutive h values per batch = 2 k-pairs
            ulonglong2 ha = *(const ulonglong2*)&h0c[g * 4];
            ulonglong2 hb = *(const ulonglong2*)&h1c[g * 4];
            ffma2(accA, ha.x, w.x);
            ffma2(accA, ha.y, w.y);
            ffma2(accB, hb.x, w.x);
            ffma2(accB, hb.y, w.y);
        }
        // register tail: k in [216, 256)
#pragma unroll
        for (int r = 0; r < KRP; r += 2) {
            ulonglong2 ha = *(const ulonglong2*)&h0c[KSM + 2 * r];
            ulonglong2 hb = *(const ulonglong2*)&h1c[KSM + 2 * r];
            ffma2(accA, ha.x, wreg[r]);
            ffma2(accA, ha.y, wreg[r + 1]);
            ffma2(accB, hb.x, wreg[r]);
            ffma2(accB, hb.y, wreg[r + 1]);
        }

        float aLo, aHi, bLo, bHi;
        f32x2_unpack(accA, aLo, aHi);
        f32x2_unpack(accB, bLo, bHi);
        float h0v = tanhf(aLo + aHi);
        float h1v = tanhf(bLo + bHi);
        h0n[j] = h0v;
        h1n[j] = h1v;
        __syncthreads();
        float* tp;
        tp = h0c; h0c = h0n; h0n = tp;
        tp = h1c; h1c = h1n; h1n = tp;
    }

    g_hfinal[(size_t)b0 * HID + j]       = h0c[j];
    g_hfinal[(size_t)(b0 + 1) * HID + j] = h1c[j];
}

// ---------------------------------------------------------------------------
// Kernel 3: out[b][o] = h_final[b][:] . fc_w[o][:] + fc_b[o]   (tiny)
// ---------------------------------------------------------------------------
__global__ __launch_bounds__(128)
void rnn_head_kernel(const float* __restrict__ fcw,
                     const float* __restrict__ fcb,
                     float* __restrict__ out) {
    __shared__ float hs[HID];
    __shared__ float part[8][OUT_DIM];
    const int b = blockIdx.x;
    const int tid = threadIdx.x;

    hs[tid]       = g_hfinal[(size_t)b * HID + tid];
    hs[tid + 128] = g_hfinal[(size_t)b * HID + tid + 128];
    __syncthreads();

    const int o   = tid & 15;
    const int seg = tid >> 4;           // 8 segments of 32
    float s = 0.f;
#pragma unroll
    for (int jj = 0; jj < 32; jj++) {
        int j = seg * 32 + jj;
        s += hs[j] * fcw[o * HID + j];
    }
    part[seg][o] = s;
    __syncthreads();
    if (tid < OUT_DIM) {
        float r = fcb[tid];
#pragma unroll
        for (int sg = 0; sg < 8; sg++) r += part[sg][tid];
        out[b * OUT_DIM + tid] = r;
    }
}

// ---------------------------------------------------------------------------
extern "C" void kernel_launch(void* const* d_in, const int* in_sizes, int n_in,
                              void* d_out, int out_size) {
    const float* x   = (const float*)d_in[0];
    const float* Wih = (const float*)d_in[1];
    const float* Whh = (const float*)d_in[2];
    const float* bh  = (const float*)d_in[3];
    const float* fcw = (const float*)d_in[4];
    const float* fcb = (const float*)d_in[5];
    float* out = (float*)d_out;

    // 1) input projection GEMM -> g_xp
    dim3 g1((BATCH * T_STEPS) / BM, HID / BN);
    gemm_xp_kernel<<<g1, 256>>>(x, Wih, bh);

    // 2) persistent batch-parallel recurrence
    cudaFuncSetAttribute(rnn_recurrence_kernel,
                         cudaFuncAttributeMaxDynamicSharedMemorySize, 225280);
    rnn_recurrence_kernel<<<BATCH / 2, 256, 225280>>>(Whh);

    // 3) classifier head
    rnn_head_kernel<<<BATCH, 128>>>(fcw, fcb, out);
}

// round 5
// speedup vs baseline: 1.1481x; 1.1481x over previous
#include <cuda_runtime.h>
#include <cuda_bf16.h>
#include <math.h>
#include <stdint.h>

// Problem constants (fixed shapes)
#define T_STEPS 2048
#define BATCH   256
#define HID     256
#define OUT_DIM 16

// Scratch (device globals: allocation-free kernel_launch)
__device__ float g_xp[134217728];          // [T][B][H] fp32, 512 MB
__device__ float g_hfinal[BATCH * HID];
__device__ __nv_bfloat16 g_xhi[134217728]; // x hi split, 256 MB
__device__ __nv_bfloat16 g_xlo[134217728]; // x lo split, 256 MB
__device__ __nv_bfloat16 g_WThi[65536];    // W_ih^T hi: [n][k]
__device__ __nv_bfloat16 g_WTlo[65536];    // W_ih^T lo: [n][k]

// ---------------------------------------------------------------------------
// helpers
// ---------------------------------------------------------------------------
__device__ __forceinline__ uint32_t smem_u32(const void* p) {
    uint32_t a;
    asm("{ .reg .u64 t; cvta.to.shared.u64 t, %1; cvt.u32.u64 %0, t; }"
        : "=r"(a) : "l"(p));
    return a;
}
__device__ __forceinline__ void cp16(uint32_t dst, const void* src) {
    asm volatile("cp.async.cg.shared.global [%0], [%1], 16;"
                 :: "r"(dst), "l"(src) : "memory");
}
__device__ __forceinline__ void ldsm_x4(uint32_t* r, uint32_t addr) {
    asm volatile("ldmatrix.sync.aligned.m8n8.x4.shared.b16 {%0,%1,%2,%3}, [%4];"
                 : "=r"(r[0]), "=r"(r[1]), "=r"(r[2]), "=r"(r[3]) : "r"(addr));
}
__device__ __forceinline__ void ldsm_x2(uint32_t* r, uint32_t addr) {
    asm volatile("ldmatrix.sync.aligned.m8n8.x2.shared.b16 {%0,%1}, [%2];"
                 : "=r"(r[0]), "=r"(r[1]) : "r"(addr));
}
__device__ __forceinline__ void mma_bf16(float* c, const uint32_t* a, const uint32_t* b) {
    asm volatile(
        "mma.sync.aligned.m16n8k16.row.col.f32.bf16.bf16.f32 "
        "{%0,%1,%2,%3}, {%4,%5,%6,%7}, {%8,%9}, {%0,%1,%2,%3};"
        : "+f"(c[0]), "+f"(c[1]), "+f"(c[2]), "+f"(c[3])
        : "r"(a[0]), "r"(a[1]), "r"(a[2]), "r"(a[3]), "r"(b[0]), "r"(b[1]));
}

// f32x2 helpers (recurrence)
__device__ __forceinline__ unsigned long long f32x2_pack(float x, float y) {
    unsigned long long r;
    asm("mov.b64 %0, {%1, %2};" : "=l"(r) : "r"(__float_as_uint(x)), "r"(__float_as_uint(y)));
    return r;
}
__device__ __forceinline__ void f32x2_unpack(unsigned long long v, float& x, float& y) {
    unsigned int lo, hi;
    asm("mov.b64 {%0, %1}, %2;" : "=r"(lo), "=r"(hi) : "l"(v));
    x = __uint_as_float(lo);
    y = __uint_as_float(hi);
}
__device__ __forceinline__ void ffma2(unsigned long long& acc,
                                      unsigned long long a, unsigned long long b) {
    asm("fma.rn.f32x2 %0, %1, %2, %0;" : "+l"(acc) : "l"(a), "l"(b));
}

// ---------------------------------------------------------------------------
// Kernel 0a: W_ih [k][n] -> transposed bf16 hi/lo [n][k]
// ---------------------------------------------------------------------------
__global__ __launch_bounds__(256)
void prep_w_kernel(const float* __restrict__ Wih) {
    int n = blockIdx.x;
    int k = threadIdx.x;
    float w = Wih[k * 256 + n];
    __nv_bfloat16 hi = __float2bfloat16(w);
    float lof = w - __bfloat162float(hi);
    g_WThi[n * 256 + k] = hi;
    g_WTlo[n * 256 + k] = __float2bfloat16(lof);
}

// ---------------------------------------------------------------------------
// Kernel 0b: x fp32 -> bf16 hi/lo splits (streaming)
// ---------------------------------------------------------------------------
__global__ __launch_bounds__(256)
void prep_x_kernel(const float* __restrict__ x) {
    size_t i = ((size_t)blockIdx.x * 256 + threadIdx.x) * 4;
    float4 f = *(const float4*)&x[i];
    __nv_bfloat162 h0 = __float22bfloat162_rn(make_float2(f.x, f.y));
    __nv_bfloat162 h1 = __float22bfloat162_rn(make_float2(f.z, f.w));
    float2 l0 = make_float2(f.x - __bfloat162float(h0.x), f.y - __bfloat162float(h0.y));
    float2 l1 = make_float2(f.z - __bfloat162float(h1.x), f.w - __bfloat162float(h1.y));
    __nv_bfloat162 lo0 = __float22bfloat162_rn(l0);
    __nv_bfloat162 lo1 = __float22bfloat162_rn(l1);
    uint2 hv, lv;
    hv.x = *(uint32_t*)&h0; hv.y = *(uint32_t*)&h1;
    lv.x = *(uint32_t*)&lo0; lv.y = *(uint32_t*)&lo1;
    *(uint2*)&g_xhi[i] = hv;
    *(uint2*)&g_xlo[i] = lv;
}

// ---------------------------------------------------------------------------
// Kernel 1: mma.sync bf16-split GEMM
// xp[m][n] = sum_k x[m][k]*W[k][n] + b_h[n], m = b*2048 + t
// CTA: 128(M) x 256(N full), 512 thr = 16 warps (2 m x 8 n), warp tile 64x32.
// K: 8 chunks of 32, cp.async double buffer.
// 3 MMAs per product: Ahi*Whi + Alo*Whi + Ahi*Wlo.
// smem per stage: Ahi,Alo [128][40]b16 + Bhi,Blo [256][40]b16 = 61440 B.
// ---------------------------------------------------------------------------
#define PADROW   40
#define AHI_OFF  0
#define ALO_OFF  10240
#define BHI_OFF  20480
#define BLO_OFF  40960
#define STAGE_B  61440
#define GSMEM    (2 * STAGE_B)

__global__ __launch_bounds__(512, 1)
void gemm_xp_mma_kernel(const float* __restrict__ bh) {
    extern __shared__ __align__(16) char dsm[];
    __shared__ float bias_s[256];

    const int tid = threadIdx.x;
    const int wid = tid >> 5;
    const int lid = tid & 31;
    const int wm  = wid & 1;        // 0..1  (m)
    const int wn  = wid >> 1;       // 0..7  (n)
    const uint32_t sb = smem_u32(dsm);

    if (tid < 256) bias_s[tid] = bh[tid];

    const size_t r0 = (size_t)blockIdx.x * 128;

    // ---- fill helper (lambda): stage s, k offset kt ----
    auto fill = [&](int s, int kt) {
        uint32_t base = sb + s * STAGE_B;
        {   // A: 512 chunks of 16B per split, 1 per thread
            int c = tid;
            int row = c >> 2, q = c & 3;
            size_t ga = (r0 + row) * 256 + kt + q * 8;
            uint32_t d = base + row * (PADROW * 2) + q * 16;
            cp16(d + AHI_OFF, g_xhi + ga);
            cp16(d + ALO_OFF, g_xlo + ga);
        }
#pragma unroll
        for (int i = 0; i < 2; i++) {  // B: 1024 chunks per split, 2 per thread
            int c = tid + i * 512;
            int row = c >> 2, q = c & 3;
            size_t gb = (size_t)row * 256 + kt + q * 8;
            uint32_t d = base + row * (PADROW * 2) + q * 16;
            cp16(d + BHI_OFF, g_WThi + gb);
            cp16(d + BLO_OFF, g_WTlo + gb);
        }
    };

    float acc[4][4][4];
#pragma unroll
    for (int mi = 0; mi < 4; mi++)
#pragma unroll
        for (int ni = 0; ni < 4; ni++)
#pragma unroll
            for (int e = 0; e < 4; e++) acc[mi][ni][e] = 0.f;

    fill(0, 0);
    asm volatile("cp.async.commit_group;" ::: "memory");
    fill(1, 32);
    asm volatile("cp.async.commit_group;" ::: "memory");

    const int arow  = wm * 64 + (lid & 15);      // A frag row (lanes 0-31)
    const int acolb = (lid >> 4) * 16;           // A frag col byte off
    const int bnrow = wn * 32 + (lid & 7);       // B frag n row (lanes 0-15 used)
    const int bkoff = ((lid >> 3) & 1) * 16;

    for (int it = 0; it < 8; it++) {
        asm volatile("cp.async.wait_group 1;" ::: "memory");
        __syncthreads();

        uint32_t As = sb + (it & 1) * STAGE_B;
        uint32_t Bs = As + BHI_OFF;

#pragma unroll
        for (int k16 = 0; k16 < 2; k16++) {
            uint32_t ahi[4][4], alo[4][4];
#pragma unroll
            for (int mi = 0; mi < 4; mi++) {
                uint32_t a = As + (arow + mi * 16) * (PADROW * 2) + k16 * 32 + acolb;
                ldsm_x4(ahi[mi], a + AHI_OFF);
                ldsm_x4(alo[mi], a + ALO_OFF);
            }
#pragma unroll
            for (int ni = 0; ni < 4; ni++) {
                uint32_t bhi[2], blo[2];
                uint32_t ba = Bs + (bnrow + ni * 8) * (PADROW * 2) + k16 * 32 + bkoff;
                ldsm_x2(bhi, ba);
                ldsm_x2(blo, ba + (BLO_OFF - BHI_OFF));
#pragma unroll
                for (int mi = 0; mi < 4; mi++) {
                    mma_bf16(acc[mi][ni], ahi[mi], bhi);
                    mma_bf16(acc[mi][ni], alo[mi], bhi);
                    mma_bf16(acc[mi][ni], ahi[mi], blo);
                }
            }
        }
        __syncthreads();
        if (it + 2 < 8) fill(it & 1, (it + 2) * 32);
        asm volatile("cp.async.commit_group;" ::: "memory");
    }

    // ---- epilogue: direct float2 stores with (t,b) remap + bias ----
#pragma unroll
    for (int mi = 0; mi < 4; mi++) {
#pragma unroll
        for (int ni = 0; ni < 4; ni++) {
            int m = wm * 64 + mi * 16 + (lid >> 2);
            int n = wn * 32 + ni * 8 + (lid & 3) * 2;
            float b0 = bias_s[n], b1 = bias_s[n + 1];
            {
                size_t r = r0 + m;
                int t = (int)(r & 2047), b = (int)(r >> 11);
                float2 v = make_float2(acc[mi][ni][0] + b0, acc[mi][ni][1] + b1);
                *(float2*)&g_xp[((size_t)t * BATCH + b) * HID + n] = v;
            }
            {
                size_t r = r0 + m + 8;
                int t = (int)(r & 2047), b = (int)(r >> 11);
                float2 v = make_float2(acc[mi][ni][2] + b0, acc[mi][ni][3] + b1);
                *(float2*)&g_xp[((size_t)t * BATCH + b) * HID + n] = v;
            }
        }
    }
}

// ---------------------------------------------------------------------------
// Kernel 2: persistent recurrence (identical to R3 passing version).
// ---------------------------------------------------------------------------
#define KSM 216
#define KG  54
#define KRG 40
#define KRP 20

__global__ __launch_bounds__(256, 1)
void rnn_recurrence_kernel(const float* __restrict__ W_hh) {
    extern __shared__ __align__(16) float smem[];
    float* Wq  = smem;
    float* h0A = smem + KSM * 256;
    float* h1A = h0A + 256;
    float* h0B = h1A + 256;
    float* h1B = h0B + 256;

    const int j  = threadIdx.x;
    const int b0 = blockIdx.x * 2;

    for (int idx = j; idx < KSM * 256; idx += 256) {
        int k  = idx >> 8;
        int jj = idx & 255;
        Wq[(k >> 2) * 1024 + jj * 4 + (k & 3)] = W_hh[idx];
    }
    unsigned long long wreg[KRP];
#pragma unroll
    for (int r = 0; r < KRP; r++)
        wreg[r] = f32x2_pack(W_hh[(KSM + 2 * r) * 256 + j],
                             W_hh[(KSM + 2 * r + 1) * 256 + j]);

    h0A[j] = 0.f;
    h1A[j] = 0.f;
    __syncthreads();

    float* h0c = h0A; float* h1c = h1A;
    float* h0n = h0B; float* h1n = h1B;

    const float* xp = g_xp + (size_t)b0 * HID + j;
    float p0 = xp[0];
    float p1 = xp[HID];

    for (int t = 0; t < T_STEPS; t++) {
        unsigned long long accA = f32x2_pack(p0, 0.f);
        unsigned long long accB = f32x2_pack(p1, 0.f);

        int tn = (t + 1 < T_STEPS) ? (t + 1) : t;
        p0 = xp[(size_t)tn * (BATCH * HID)];
        p1 = xp[(size_t)tn * (BATCH * HID) + HID];

        const unsigned long long* wp = (const unsigned long long*)(Wq + j * 4);
#pragma unroll 6
        for (int g = 0; g < KG; g++) {
            ulonglong2 w  = *(const ulonglong2*)&wp[g * 512];
            ulonglong2 ha = *(const ulonglong2*)&h0c[g * 4];
            ulonglong2 hb = *(const ulonglong2*)&h1c[g * 4];
            ffma2(accA, ha.x, w.x);
            ffma2(accA, ha.y, w.y);
            ffma2(accB, hb.x, w.x);
            ffma2(accB, hb.y, w.y);
        }
#pragma unroll
        for (int r = 0; r < KRP; r += 2) {
            ulonglong2 ha = *(const ulonglong2*)&h0c[KSM + 2 * r];
            ulonglong2 hb = *(const ulonglong2*)&h1c[KSM + 2 * r];
            ffma2(accA, ha.x, wreg[r]);
            ffma2(accA, ha.y, wreg[r + 1]);
            ffma2(accB, hb.x, wreg[r]);
            ffma2(accB, hb.y, wreg[r + 1]);
        }

        float aLo, aHi, bLo, bHi;
        f32x2_unpack(accA, aLo, aHi);
        f32x2_unpack(accB, bLo, bHi);
        float h0v = tanhf(aLo + aHi);
        float h1v = tanhf(bLo + bHi);
        h0n[j] = h0v;
        h1n[j] = h1v;
        __syncthreads();
        float* tp;
        tp = h0c; h0c = h0n; h0n = tp;
        tp = h1c; h1c = h1n; h1n = tp;
    }

    g_hfinal[(size_t)b0 * HID + j]       = h0c[j];
    g_hfinal[(size_t)(b0 + 1) * HID + j] = h1c[j];
}

// ---------------------------------------------------------------------------
// Kernel 3: classifier head (tiny)
// ---------------------------------------------------------------------------
__global__ __launch_bounds__(128)
void rnn_head_kernel(const float* __restrict__ fcw,
                     const float* __restrict__ fcb,
                     float* __restrict__ out) {
    __shared__ float hs[HID];
    __shared__ float part[8][OUT_DIM];
    const int b = blockIdx.x;
    const int tid = threadIdx.x;

    hs[tid]       = g_hfinal[(size_t)b * HID + tid];
    hs[tid + 128] = g_hfinal[(size_t)b * HID + tid + 128];
    __syncthreads();

    const int o   = tid & 15;
    const int seg = tid >> 4;
    float s = 0.f;
#pragma unroll
    for (int jj = 0; jj < 32; jj++) {
        int j = seg * 32 + jj;
        s += hs[j] * fcw[o * HID + j];
    }
    part[seg][o] = s;
    __syncthreads();
    if (tid < OUT_DIM) {
        float r = fcb[tid];
#pragma unroll
        for (int sg = 0; sg < 8; sg++) r += part[sg][tid];
        out[b * OUT_DIM + tid] = r;
    }
}

// ---------------------------------------------------------------------------
extern "C" void kernel_launch(void* const* d_in, const int* in_sizes, int n_in,
                              void* d_out, int out_size) {
    const float* x   = (const float*)d_in[0];
    const float* Wih = (const float*)d_in[1];
    const float* Whh = (const float*)d_in[2];
    const float* bh  = (const float*)d_in[3];
    const float* fcw = (const float*)d_in[4];
    const float* fcb = (const float*)d_in[5];
    float* out = (float*)d_out;

    // 0) bf16 hi/lo splits of W_ih^T and x
    prep_w_kernel<<<256, 256>>>(Wih);
    prep_x_kernel<<<131072, 256>>>(x);

    // 1) input projection GEMM on tensor cores (mma.sync) -> g_xp
    cudaFuncSetAttribute(gemm_xp_mma_kernel,
                         cudaFuncAttributeMaxDynamicSharedMemorySize, GSMEM);
    gemm_xp_mma_kernel<<<(BATCH * T_STEPS) / 128, 512, GSMEM>>>(bh);

    // 2) persistent batch-parallel recurrence
    cudaFuncSetAttribute(rnn_recurrence_kernel,
                         cudaFuncAttributeMaxDynamicSharedMemorySize, 225280);
    rnn_recurrence_kernel<<<BATCH / 2, 256, 225280>>>(Whh);

    // 3) classifier head
    rnn_head_kernel<<<BATCH, 128>>>(fcw, fcb, out);
}

// round 6
// speedup vs baseline: 1.1502x; 1.0019x over previous
#include <cuda_runtime.h>
#include <cuda_bf16.h>
#include <math.h>
#include <stdint.h>

// Problem constants (fixed shapes)
#define T_STEPS 2048
#define BATCH   256
#define HID     256
#define OUT_DIM 16

// Scratch (device globals: allocation-free kernel_launch)
__device__ float g_xp[134217728];          // [T][B][H] fp32, 512 MB
__device__ float g_hfinal[BATCH * HID];
__device__ __nv_bfloat16 g_xhi[134217728]; // x hi split, 256 MB
__device__ __nv_bfloat16 g_xlo[134217728]; // x lo split, 256 MB
__device__ __nv_bfloat16 g_WThi[65536];    // W_ih^T hi: [n][k]
__device__ __nv_bfloat16 g_WTlo[65536];    // W_ih^T lo: [n][k]

// ---------------------------------------------------------------------------
// helpers
// ---------------------------------------------------------------------------
__device__ __forceinline__ uint32_t smem_u32(const void* p) {
    uint32_t a;
    asm("{ .reg .u64 t; cvta.to.shared.u64 t, %1; cvt.u32.u64 %0, t; }"
        : "=r"(a) : "l"(p));
    return a;
}
__device__ __forceinline__ void cp16(uint32_t dst, const void* src) {
    asm volatile("cp.async.cg.shared.global [%0], [%1], 16;"
                 :: "r"(dst), "l"(src) : "memory");
}
__device__ __forceinline__ void ldsm_x4(uint32_t* r, uint32_t addr) {
    asm volatile("ldmatrix.sync.aligned.m8n8.x4.shared.b16 {%0,%1,%2,%3}, [%4];"
                 : "=r"(r[0]), "=r"(r[1]), "=r"(r[2]), "=r"(r[3]) : "r"(addr));
}
__device__ __forceinline__ void ldsm_x2(uint32_t* r, uint32_t addr) {
    asm volatile("ldmatrix.sync.aligned.m8n8.x2.shared.b16 {%0,%1}, [%2];"
                 : "=r"(r[0]), "=r"(r[1]) : "r"(addr));
}
__device__ __forceinline__ void mma_bf16(float* c, const uint32_t* a, const uint32_t* b) {
    asm volatile(
        "mma.sync.aligned.m16n8k16.row.col.f32.bf16.bf16.f32 "
        "{%0,%1,%2,%3}, {%4,%5,%6,%7}, {%8,%9}, {%0,%1,%2,%3};"
        : "+f"(c[0]), "+f"(c[1]), "+f"(c[2]), "+f"(c[3])
        : "r"(a[0]), "r"(a[1]), "r"(a[2]), "r"(a[3]), "r"(b[0]), "r"(b[1]));
}

// f32x2 helpers (recurrence)
__device__ __forceinline__ unsigned long long f32x2_pack(float x, float y) {
    unsigned long long r;
    asm("mov.b64 %0, {%1, %2};" : "=l"(r) : "r"(__float_as_uint(x)), "r"(__float_as_uint(y)));
    return r;
}
__device__ __forceinline__ void f32x2_unpack(unsigned long long v, float& x, float& y) {
    unsigned int lo, hi;
    asm("mov.b64 {%0, %1}, %2;" : "=r"(lo), "=r"(hi) : "l"(v));
    x = __uint_as_float(lo);
    y = __uint_as_float(hi);
}
__device__ __forceinline__ void ffma2(unsigned long long& acc,
                                      unsigned long long a, unsigned long long b) {
    asm("fma.rn.f32x2 %0, %1, %2, %0;" : "+l"(acc) : "l"(a), "l"(b));
}
__device__ __forceinline__ void fadd2(unsigned long long& acc, unsigned long long b) {
    asm("add.rn.f32x2 %0, %0, %1;" : "+l"(acc) : "l"(b));
}

// ---------------------------------------------------------------------------
// Kernel 0a: W_ih [k][n] -> transposed bf16 hi/lo [n][k]
// ---------------------------------------------------------------------------
__global__ __launch_bounds__(256)
void prep_w_kernel(const float* __restrict__ Wih) {
    int n = blockIdx.x;
    int k = threadIdx.x;
    float w = Wih[k * 256 + n];
    __nv_bfloat16 hi = __float2bfloat16(w);
    float lof = w - __bfloat162float(hi);
    g_WThi[n * 256 + k] = hi;
    g_WTlo[n * 256 + k] = __float2bfloat16(lof);
}

// ---------------------------------------------------------------------------
// Kernel 0b: x fp32 -> bf16 hi/lo splits (streaming)
// ---------------------------------------------------------------------------
__global__ __launch_bounds__(256)
void prep_x_kernel(const float* __restrict__ x) {
    size_t i = ((size_t)blockIdx.x * 256 + threadIdx.x) * 4;
    float4 f = *(const float4*)&x[i];
    __nv_bfloat162 h0 = __float22bfloat162_rn(make_float2(f.x, f.y));
    __nv_bfloat162 h1 = __float22bfloat162_rn(make_float2(f.z, f.w));
    float2 l0 = make_float2(f.x - __bfloat162float(h0.x), f.y - __bfloat162float(h0.y));
    float2 l1 = make_float2(f.z - __bfloat162float(h1.x), f.w - __bfloat162float(h1.y));
    __nv_bfloat162 lo0 = __float22bfloat162_rn(l0);
    __nv_bfloat162 lo1 = __float22bfloat162_rn(l1);
    uint2 hv, lv;
    hv.x = *(uint32_t*)&h0; hv.y = *(uint32_t*)&h1;
    lv.x = *(uint32_t*)&lo0; lv.y = *(uint32_t*)&lo1;
    *(uint2*)&g_xhi[i] = hv;
    *(uint2*)&g_xlo[i] = lv;
}

// ---------------------------------------------------------------------------
// Kernel 1: mma.sync bf16-split GEMM (unchanged from R5 passing version)
// ---------------------------------------------------------------------------
#define PADROW   40
#define AHI_OFF  0
#define ALO_OFF  10240
#define BHI_OFF  20480
#define BLO_OFF  40960
#define STAGE_B  61440
#define GSMEM    (2 * STAGE_B)

__global__ __launch_bounds__(512, 1)
void gemm_xp_mma_kernel(const float* __restrict__ bh) {
    extern __shared__ __align__(16) char dsm[];
    __shared__ float bias_s[256];

    const int tid = threadIdx.x;
    const int wid = tid >> 5;
    const int lid = tid & 31;
    const int wm  = wid & 1;
    const int wn  = wid >> 1;
    const uint32_t sb = smem_u32(dsm);

    if (tid < 256) bias_s[tid] = bh[tid];

    const size_t r0 = (size_t)blockIdx.x * 128;

    auto fill = [&](int s, int kt) {
        uint32_t base = sb + s * STAGE_B;
        {
            int c = tid;
            int row = c >> 2, q = c & 3;
            size_t ga = (r0 + row) * 256 + kt + q * 8;
            uint32_t d = base + row * (PADROW * 2) + q * 16;
            cp16(d + AHI_OFF, g_xhi + ga);
            cp16(d + ALO_OFF, g_xlo + ga);
        }
#pragma unroll
        for (int i = 0; i < 2; i++) {
            int c = tid + i * 512;
            int row = c >> 2, q = c & 3;
            size_t gb = (size_t)row * 256 + kt + q * 8;
            uint32_t d = base + row * (PADROW * 2) + q * 16;
            cp16(d + BHI_OFF, g_WThi + gb);
            cp16(d + BLO_OFF, g_WTlo + gb);
        }
    };

    float acc[4][4][4];
#pragma unroll
    for (int mi = 0; mi < 4; mi++)
#pragma unroll
        for (int ni = 0; ni < 4; ni++)
#pragma unroll
            for (int e = 0; e < 4; e++) acc[mi][ni][e] = 0.f;

    fill(0, 0);
    asm volatile("cp.async.commit_group;" ::: "memory");
    fill(1, 32);
    asm volatile("cp.async.commit_group;" ::: "memory");

    const int arow  = wm * 64 + (lid & 15);
    const int acolb = (lid >> 4) * 16;
    const int bnrow = wn * 32 + (lid & 7);
    const int bkoff = ((lid >> 3) & 1) * 16;

    for (int it = 0; it < 8; it++) {
        asm volatile("cp.async.wait_group 1;" ::: "memory");
        __syncthreads();

        uint32_t As = sb + (it & 1) * STAGE_B;
        uint32_t Bs = As + BHI_OFF;

#pragma unroll
        for (int k16 = 0; k16 < 2; k16++) {
            uint32_t ahi[4][4], alo[4][4];
#pragma unroll
            for (int mi = 0; mi < 4; mi++) {
                uint32_t a = As + (arow + mi * 16) * (PADROW * 2) + k16 * 32 + acolb;
                ldsm_x4(ahi[mi], a + AHI_OFF);
                ldsm_x4(alo[mi], a + ALO_OFF);
            }
#pragma unroll
            for (int ni = 0; ni < 4; ni++) {
                uint32_t bhi[2], blo[2];
                uint32_t ba = Bs + (bnrow + ni * 8) * (PADROW * 2) + k16 * 32 + bkoff;
                ldsm_x2(bhi, ba);
                ldsm_x2(blo, ba + (BLO_OFF - BHI_OFF));
#pragma unroll
                for (int mi = 0; mi < 4; mi++) {
                    mma_bf16(acc[mi][ni], ahi[mi], bhi);
                    mma_bf16(acc[mi][ni], alo[mi], bhi);
                    mma_bf16(acc[mi][ni], ahi[mi], blo);
                }
            }
        }
        __syncthreads();
        if (it + 2 < 8) fill(it & 1, (it + 2) * 32);
        asm volatile("cp.async.commit_group;" ::: "memory");
    }

#pragma unroll
    for (int mi = 0; mi < 4; mi++) {
#pragma unroll
        for (int ni = 0; ni < 4; ni++) {
            int m = wm * 64 + mi * 16 + (lid >> 2);
            int n = wn * 32 + ni * 8 + (lid & 3) * 2;
            float b0 = bias_s[n], b1 = bias_s[n + 1];
            {
                size_t r = r0 + m;
                int t = (int)(r & 2047), b = (int)(r >> 11);
                float2 v = make_float2(acc[mi][ni][0] + b0, acc[mi][ni][1] + b1);
                *(float2*)&g_xp[((size_t)t * BATCH + b) * HID + n] = v;
            }
            {
                size_t r = r0 + m + 8;
                int t = (int)(r & 2047), b = (int)(r >> 11);
                float2 v = make_float2(acc[mi][ni][2] + b0, acc[mi][ni][3] + b1);
                *(float2*)&g_xp[((size_t)t * BATCH + b) * HID + n] = v;
            }
        }
    }
}

// ---------------------------------------------------------------------------
// Kernel 2: persistent recurrence with 4 independent accumulator chains per
// batch (8 u64 chains/thread) to break ffma2 RAW latency chains.
// 128 CTAs, 2 batches each, 256 threads; W rows [0,216) smem, [216,256) regs.
// ---------------------------------------------------------------------------
#define KSM 216
#define KG  54
#define KRG 40
#define KRP 20

__global__ __launch_bounds__(256, 1)
void rnn_recurrence_kernel(const float* __restrict__ W_hh) {
    extern __shared__ __align__(16) float smem[];
    float* Wq  = smem;
    float* h0A = smem + KSM * 256;
    float* h1A = h0A + 256;
    float* h0B = h1A + 256;
    float* h1B = h0B + 256;

    const int j  = threadIdx.x;
    const int b0 = blockIdx.x * 2;

    for (int idx = j; idx < KSM * 256; idx += 256) {
        int k  = idx >> 8;
        int jj = idx & 255;
        Wq[(k >> 2) * 1024 + jj * 4 + (k & 3)] = W_hh[idx];
    }
    unsigned long long wreg[KRP];
#pragma unroll
    for (int r = 0; r < KRP; r++)
        wreg[r] = f32x2_pack(W_hh[(KSM + 2 * r) * 256 + j],
                             W_hh[(KSM + 2 * r + 1) * 256 + j]);

    h0A[j] = 0.f;
    h1A[j] = 0.f;
    __syncthreads();

    float* h0c = h0A; float* h1c = h1A;
    float* h0n = h0B; float* h1n = h1B;

    const float* xp = g_xp + (size_t)b0 * HID + j;
    float p0 = xp[0];
    float p1 = xp[HID];

    for (int t = 0; t < T_STEPS; t++) {
        // 4 independent chains per batch
        unsigned long long aA[4], aB[4];
        aA[0] = f32x2_pack(p0, 0.f); aA[1] = 0ull; aA[2] = 0ull; aA[3] = 0ull;
        aB[0] = f32x2_pack(p1, 0.f); aB[1] = 0ull; aB[2] = 0ull; aB[3] = 0ull;

        int tn = (t + 1 < T_STEPS) ? (t + 1) : t;
        p0 = xp[(size_t)tn * (BATCH * HID)];
        p1 = xp[(size_t)tn * (BATCH * HID) + HID];

        const unsigned long long* wp = (const unsigned long long*)(Wq + j * 4);
#pragma unroll 6
        for (int g = 0; g < KG; g++) {
            ulonglong2 w  = *(const ulonglong2*)&wp[g * 512];
            ulonglong2 ha = *(const ulonglong2*)&h0c[g * 4];
            ulonglong2 hb = *(const ulonglong2*)&h1c[g * 4];
            const int c0 = (2 * g) & 3;
            const int c1 = (2 * g + 1) & 3;
            ffma2(aA[c0], ha.x, w.x);
            ffma2(aA[c1], ha.y, w.y);
            ffma2(aB[c0], hb.x, w.x);
            ffma2(aB[c1], hb.y, w.y);
        }
        // register tail: k in [216, 256)
#pragma unroll
        for (int r = 0; r < KRP; r++) {
            unsigned long long ha = *(const unsigned long long*)&h0c[KSM + 2 * r];
            unsigned long long hb = *(const unsigned long long*)&h1c[KSM + 2 * r];
            const int c = r & 3;
            ffma2(aA[c], ha, wreg[r]);
            ffma2(aB[c], hb, wreg[r]);
        }

        // tree-sum the chains
        fadd2(aA[0], aA[1]); fadd2(aA[2], aA[3]); fadd2(aA[0], aA[2]);
        fadd2(aB[0], aB[1]); fadd2(aB[2], aB[3]); fadd2(aB[0], aB[2]);

        float aLo, aHi, bLo, bHi;
        f32x2_unpack(aA[0], aLo, aHi);
        f32x2_unpack(aB[0], bLo, bHi);
        float h0v = tanhf(aLo + aHi);
        float h1v = tanhf(bLo + bHi);
        h0n[j] = h0v;
        h1n[j] = h1v;
        __syncthreads();
        float* tp;
        tp = h0c; h0c = h0n; h0n = tp;
        tp = h1c; h1c = h1n; h1n = tp;
    }

    g_hfinal[(size_t)b0 * HID + j]       = h0c[j];
    g_hfinal[(size_t)(b0 + 1) * HID + j] = h1c[j];
}

// ---------------------------------------------------------------------------
// Kernel 3: classifier head (tiny)
// ---------------------------------------------------------------------------
__global__ __launch_bounds__(128)
void rnn_head_kernel(const float* __restrict__ fcw,
                     const float* __restrict__ fcb,
                     float* __restrict__ out) {
    __shared__ float hs[HID];
    __shared__ float part[8][OUT_DIM];
    const int b = blockIdx.x;
    const int tid = threadIdx.x;

    hs[tid]       = g_hfinal[(size_t)b * HID + tid];
    hs[tid + 128] = g_hfinal[(size_t)b * HID + tid + 128];
    __syncthreads();

    const int o   = tid & 15;
    const int seg = tid >> 4;
    float s = 0.f;
#pragma unroll
    for (int jj = 0; jj < 32; jj++) {
        int j = seg * 32 + jj;
        s += hs[j] * fcw[o * HID + j];
    }
    part[seg][o] = s;
    __syncthreads();
    if (tid < OUT_DIM) {
        float r = fcb[tid];
#pragma unroll
        for (int sg = 0; sg < 8; sg++) r += part[sg][tid];
        out[b * OUT_DIM + tid] = r;
    }
}

// ---------------------------------------------------------------------------
extern "C" void kernel_launch(void* const* d_in, const int* in_sizes, int n_in,
                              void* d_out, int out_size) {
    const float* x   = (const float*)d_in[0];
    const float* Wih = (const float*)d_in[1];
    const float* Whh = (const float*)d_in[2];
    const float* bh  = (const float*)d_in[3];
    const float* fcw = (const float*)d_in[4];
    const float* fcb = (const float*)d_in[5];
    float* out = (float*)d_out;

    // 0) bf16 hi/lo splits of W_ih^T and x
    prep_w_kernel<<<256, 256>>>(Wih);
    prep_x_kernel<<<131072, 256>>>(x);

    // 1) input projection GEMM on tensor cores (mma.sync) -> g_xp
    cudaFuncSetAttribute(gemm_xp_mma_kernel,
                         cudaFuncAttributeMaxDynamicSharedMemorySize, GSMEM);
    gemm_xp_mma_kernel<<<(BATCH * T_STEPS) / 128, 512, GSMEM>>>(bh);

    // 2) persistent batch-parallel recurrence
    cudaFuncSetAttribute(rnn_recurrence_kernel,
                         cudaFuncAttributeMaxDynamicSharedMemorySize, 225280);
    rnn_recurrence_kernel<<<BATCH / 2, 256, 225280>>>(Whh);

    // 3) classifier head
    rnn_head_kernel<<<BATCH, 128>>>(fcw, fcb, out);
}